// round 15
// baseline (speedup 1.0000x reference)
#include <cuda_runtime.h>

#define VDIM   50257
#define BDIM   2048
#define KSEL   500
#define NTH    256
#define NW     8
#define LISTCAP 4096
#define SVCH   4            // 4 chunks * 256 threads * float4 = 4096 samples
#define ZCOEF  1.95f
#define MARGIN_C 0.2f
#define IGNORE_IDX 0
#define FULLM 0xffffffffu
#define NCTA   296          // 148 SMs * 2 CTAs (smem-bound occupancy)
#define CHUNKF4 1024        // float4 per chunk = 4096 floats = 16 KB
#define CHUNK   4096        // floats per chunk

__device__ float    g_rowloss[BDIM];
__device__ unsigned g_done;
__device__ unsigned g_row;

static __device__ __forceinline__ unsigned fkey(float f){
    unsigned u = __float_as_uint(f);
    return (u & 0x80000000u) ? ~u : (u | 0x80000000u);
}
static __device__ __forceinline__ float kinv(unsigned u){
    unsigned b = (u & 0x80000000u) ? (u & 0x7FFFFFFFu) : ~u;
    return __uint_as_float(b);
}
static __device__ __forceinline__ unsigned smem_u32(const void* p){
    unsigned a;
    asm("{ .reg .u64 t; cvta.to.shared.u64 t, %1; cvt.u32.u64 %0, t; }" : "=r"(a) : "l"(p));
    return a;
}

#define MBAR_INIT(mb, cnt) \
    asm volatile("mbarrier.init.shared.b64 [%0], %1;" :: "r"(mb), "r"(cnt) : "memory")
#define MBAR_EXPECT_TX(mb, bytes) \
    asm volatile("mbarrier.arrive.expect_tx.shared.b64 _, [%0], %1;" :: "r"(mb), "r"(bytes) : "memory")
#define TMA_BULK(dst, src, bytes, mb) \
    asm volatile("cp.async.bulk.shared::cta.global.mbarrier::complete_tx::bytes [%0], [%1], %2, [%3];" \
        :: "r"(dst), "l"(src), "r"(bytes), "r"(mb) : "memory")
#define MBAR_WAIT(mb, ph) do { \
    unsigned _mb = (mb); unsigned _ph = (ph); unsigned _done; \
    asm volatile("{\n\t.reg .pred p;\n\t" \
        "mbarrier.try_wait.parity.acquire.cta.shared::cta.b64 p, [%1], %2;\n\t" \
        "selp.b32 %0, 1, 0, p;\n\t}" : "=r"(_done) : "r"(_mb), "r"(_ph) : "memory"); \
    if (!_done){ \
        asm volatile("{\n\t.reg .pred P1;\n\t" \
            "WL_%=:\n\t" \
            "mbarrier.try_wait.parity.acquire.cta.shared::cta.b64 P1, [%0], %1, 0x989680;\n\t" \
            "@P1 bra.uni WD_%=;\n\t" \
            "bra.uni WL_%=;\n\t" \
            "WD_%=:\n\t}" :: "r"(_mb), "r"(_ph) : "memory"); \
    } \
} while(0)

static __device__ __forceinline__ void select_bucket(
    const unsigned* hists, unsigned& kk, unsigned& bucket,
    unsigned* wtot, unsigned* selb, unsigned* selk)
{
    const int tid = threadIdx.x;
    const int lane = tid & 31;
    unsigned cnt = hists[tid];
    unsigned s = cnt;
    #pragma unroll
    for (int o = 1; o < 32; o <<= 1){
        unsigned t = __shfl_down_sync(FULLM, s, o);
        if (lane + o < 32) s += t;
    }
    if (lane == 0) wtot[tid >> 5] = s;
    __syncthreads();
    unsigned Sb = s;
    for (int w = (tid >> 5) + 1; w < 8; ++w) Sb += wtot[w];
    unsigned Snext = Sb - cnt;
    if (Sb >= kk && Snext < kk){ *selb = (unsigned)tid; *selk = kk - Snext; }
    __syncthreads();
    bucket = *selb;
    kk = *selk;
    __syncthreads();
}

static __device__ unsigned radix_select(const unsigned* keys, int n, unsigned kk,
                                        unsigned* hists, unsigned* wtot,
                                        unsigned* selb, unsigned* selk)
{
    const int tid = threadIdx.x;
    const int lane = tid & 31;
    unsigned prefix = 0;
    for (int shift = 24; shift >= 0; shift -= 8){
        hists[tid] = 0;
        __syncthreads();
        const bool first = (shift == 24);
        const unsigned pref_hi = first ? 0u : (prefix >> (shift + 8));
        const int nit = (n + NTH - 1) / NTH;
        for (int it = 0; it < nit; ++it){
            int i = it*NTH + tid;
            bool in = i < n;
            unsigned u = in ? keys[i] : 0u;
            bool okd = in && (first || (u >> (shift + 8)) == pref_hi);
            unsigned d = (u >> shift) & 255u;
            unsigned tag = okd ? d : (0x100u + (unsigned)lane);
            unsigned mm = __match_any_sync(FULLM, tag);
            if (okd && lane == (__ffs(mm) - 1))
                atomicAdd(&hists[d], (unsigned)__popc(mm));
        }
        __syncthreads();
        unsigned b;
        select_bucket(hists, kk, b, wtot, selb, selk);
        prefix |= b << shift;
    }
    return prefix;
}

__global__ void __launch_bounds__(NTH)
adalab_kernel(const float* __restrict__ output,
              const int*   __restrict__ target,
              const float* __restrict__ scores,
              float* __restrict__ out)
{
    extern __shared__ float dynf[];
    // dynamic smem layout:
    float*    obuf[2] = { dynf,             dynf + CHUNK };
    float*    sbuf[2] = { dynf + 2*CHUNK,   dynf + 3*CHUNK };
    unsigned* lkey    = reinterpret_cast<unsigned*>(dynf + 4*CHUNK);
    float*    lout    = dynf + 4*CHUNK + LISTCAP;

    __shared__ unsigned long long s_mbar[2];
    __shared__ unsigned hists[256];
    __shared__ float    s_f0[NW], s_f1[NW], s_f2[NW];
    __shared__ unsigned s_t2a[NW], s_t2b[NW];
    __shared__ unsigned s_wtot[8];
    __shared__ unsigned s_selb, s_selk;
    __shared__ int      s_nlist;
    __shared__ float    s_ot, s_stgt, s_s0, s_o0;
    __shared__ int      s_rm;
    __shared__ int      s_last;
    __shared__ int      s_row;

    const int tid  = threadIdx.x;
    const int lane = tid & 31;
    const int wid  = tid >> 5;
    const float NEGINF = __int_as_float(0xff800000);

    const unsigned mbar0 = smem_u32(&s_mbar[0]);
    const unsigned mbar1 = smem_u32(&s_mbar[1]);
    const unsigned ob_addr[2] = { smem_u32(obuf[0]), smem_u32(obuf[1]) };
    const unsigned sb_addr[2] = { smem_u32(sbuf[0]), smem_u32(sbuf[1]) };

    if (tid == 0){ MBAR_INIT(mbar0, 1); MBAR_INIT(mbar1, 1); }
    __syncthreads();
    unsigned ph[2] = {0u, 0u};

    while (true){
        __syncthreads();
        if (tid == 0) s_row = (int)atomicAdd(&g_row, 1u);
        __syncthreads();
        const int row = s_row;
        if (row >= BDIM) break;

        const int tgt  = target[row];
        const float* orow = output + (size_t)row * VDIM;
        const float* srow = scores + (size_t)row * VDIM;

        const int a    = (int)((4u - ((unsigned)((size_t)row * VDIM) & 3u)) & 3u);
        const int nvec = (VDIM - a) >> 2;
        const int vend = a + nvec * 4;
        const int nchunks = (nvec + CHUNKF4 - 1) / CHUNKF4;

        if (tid == 0){
            s_ot   = __ldg(orow + tgt);
            s_stgt = __ldg(srow + tgt);
            s_s0   = __ldg(srow + IGNORE_IDX);
            s_o0   = __ldg(orow + IGNORE_IDX);
            s_nlist = 0;
        }

        // ---- kick off pipeline: chunks 0 and 1 ----
        if (tid == 0){
            #pragma unroll
            for (int c = 0; c < 2; ++c){
                if (c < nchunks){
                    int off = c * CHUNKF4;
                    int nf4 = min(CHUNKF4, nvec - off);
                    unsigned bytes = (unsigned)nf4 * 16u;
                    unsigned mb = c ? mbar1 : mbar0;
                    MBAR_EXPECT_TX(mb, bytes * 2u);
                    TMA_BULK(ob_addr[c], orow + a + off*4, bytes, mb);
                    TMA_BULK(sb_addr[c], srow + a + off*4, bytes, mb);
                }
            }
        }

        // ------- sample pass (LDG, tiny): mean + ZCOEF*sigma of 4096 samples ----
        float sum = 0.f, sq = 0.f;
        #pragma unroll
        for (int c = 0; c < SVCH; ++c){
            int qb = (c * (nvec - NTH)) / (SVCH - 1);
            float4 s4 = __ldg(reinterpret_cast<const float4*>(srow + a + (qb + tid)*4));
            sum += (s4.x + s4.y) + (s4.z + s4.w);
            sq = fmaf(s4.x, s4.x, sq); sq = fmaf(s4.y, s4.y, sq);
            sq = fmaf(s4.z, s4.z, sq); sq = fmaf(s4.w, s4.w, sq);
        }
        #pragma unroll
        for (int o = 16; o; o >>= 1){
            sum += __shfl_xor_sync(FULLM, sum, o);
            sq  += __shfl_xor_sync(FULLM, sq,  o);
        }
        if (!lane){ s_f1[wid] = sum; s_f2[wid] = sq; }
        __syncthreads();
        if (wid == 0){
            float u = (lane < NW) ? s_f1[lane] : 0.f;
            float v = (lane < NW) ? s_f2[lane] : 0.f;
            #pragma unroll
            for (int o = 4; o; o >>= 1){
                u += __shfl_xor_sync(FULLM, u, o);
                v += __shfl_xor_sync(FULLM, v, o);
            }
            if (!lane){ s_f1[0] = u; s_f2[0] = v; }
        }
        __syncthreads();
        {
            const float inv_n = 1.0f / (SVCH * NTH * 4);
            float mean = s_f1[0] * inv_n;
            float var  = fmaxf(s_f2[0] * inv_n - mean*mean, 1e-12f);
            if (tid == 0) s_f0[0] = mean + ZCOEF * sqrtf(var);
        }
        __syncthreads();
        unsigned tkey = fkey(s_f0[0]);
        const float T = kinv(tkey);

        // -------- streaming: consume TMA-staged chunks (omax + compaction) ------
        float omax = NEGINF;
        {
            // scalar prologue / epilogue via LDG
            int j = tid;
            if (j < a){
                float o = __ldg(orow + j); omax = fmaxf(omax, o);
                float sv = __ldg(srow + j);
                if (sv >= T){
                    int pos = atomicAdd(&s_nlist, 1);
                    if (pos < LISTCAP){ lkey[pos] = fkey(sv); lout[pos] = o; }
                }
            }
            j = vend + tid;
            if (j < VDIM){
                float o = __ldg(orow + j); omax = fmaxf(omax, o);
                float sv = __ldg(srow + j);
                if (sv >= T){
                    int pos = atomicAdd(&s_nlist, 1);
                    if (pos < LISTCAP){ lkey[pos] = fkey(sv); lout[pos] = o; }
                }
            }

            for (int c = 0; c < nchunks; ++c){
                int b = c & 1;
                MBAR_WAIT(b ? mbar1 : mbar0, ph[b]);
                ph[b] ^= 1;
                int nf4 = min(CHUNKF4, nvec - c*CHUNKF4);
                const float4* of4 = reinterpret_cast<const float4*>(obuf[b]);
                const float4* sf4 = reinterpret_cast<const float4*>(sbuf[b]);
                #pragma unroll 4
                for (int i = tid; i < nf4; i += NTH){
                    float4 o4 = of4[i];
                    float4 s4 = sf4[i];
                    omax = fmaxf(omax, fmaxf(fmaxf(o4.x, o4.y), fmaxf(o4.z, o4.w)));
                    #define EMIT(sv, ov) \
                        if ((sv) >= T){ \
                            int pos = atomicAdd(&s_nlist, 1); \
                            if (pos < LISTCAP){ lkey[pos] = fkey(sv); lout[pos] = (ov); } \
                        }
                    EMIT(s4.x, o4.x) EMIT(s4.y, o4.y) EMIT(s4.z, o4.z) EMIT(s4.w, o4.w)
                    #undef EMIT
                }
                __syncthreads();       // all reads of buffer b done before refill
                if (tid == 0 && c + 2 < nchunks){
                    int c2 = c + 2;
                    int off = c2 * CHUNKF4;
                    int nf2 = min(CHUNKF4, nvec - off);
                    unsigned bytes = (unsigned)nf2 * 16u;
                    unsigned mb = b ? mbar1 : mbar0;
                    MBAR_EXPECT_TX(mb, bytes * 2u);
                    TMA_BULK(ob_addr[b], orow + a + off*4, bytes, mb);
                    TMA_BULK(sb_addr[b], srow + a + off*4, bytes, mb);
                }
            }
        }
        // reduce omax
        #pragma unroll
        for (int o = 16; o; o >>= 1) omax = fmaxf(omax, __shfl_xor_sync(FULLM, omax, o));
        if (!lane) s_f0[wid] = omax;
        __syncthreads();
        if (wid == 0){
            float x = (lane < NW) ? s_f0[lane] : NEGINF;
            #pragma unroll
            for (int o = 4; o; o >>= 1) x = fmaxf(x, __shfl_xor_sync(FULLM, x, o));
            if (!lane) s_f0[0] = x;
        }
        __syncthreads();
        const float o_max = s_f0[0];
        const float o_t   = s_ot;

        int nl = s_nlist;

        // ------------- exact removal of tgt / ignore entries (if captured) -------
        if (nl <= LISTCAP){
            #pragma unroll
            for (int vsel = 0; vsel < 2; ++vsel){
                if (vsel == 1 && tgt == IGNORE_IDX) break;
                float svict = (vsel == 0) ? s_stgt : s_s0;
                float ovict = (vsel == 0) ? s_ot   : s_o0;
                if (svict >= T){
                    unsigned kv = fkey(svict);
                    __syncthreads();
                    if (tid == 0) s_rm = 0x7fffffff;
                    __syncthreads();
                    for (int i = tid; i < nl; i += NTH)
                        if (lkey[i] == kv && lout[i] == ovict) atomicMin(&s_rm, i);
                    __syncthreads();
                    int rm = s_rm;
                    if (tid == 0 && rm < nl){
                        lkey[rm] = lkey[nl-1]; lout[rm] = lout[nl-1];
                        s_nlist = nl - 1;
                    }
                    __syncthreads();
                    nl = s_nlist;
                }
            }
        }
        bool ok = (nl >= KSEL && nl <= LISTCAP);
        unsigned tk2 = tkey;

        // ------------- rare: binary-search rescan on threshold key ---------------
        if (!ok){
            unsigned lo = 0u, hi = 0xffffffffu;
            if (nl > LISTCAP) lo = tk2; else hi = tk2;
            for (int iter = 0; iter < 12 && hi - lo >= 2u; ++iter){
                tk2 = lo + ((hi - lo) >> 1);
                __syncthreads();
                if (tid == 0) s_nlist = 0;
                __syncthreads();
                const float T2 = kinv(tk2);
                for (int j = tid; j < VDIM; j += NTH){
                    float sv = srow[j];
                    if (sv >= T2 && j != tgt && j != IGNORE_IDX){
                        int pos = atomicAdd(&s_nlist, 1);
                        if (pos < LISTCAP){ lkey[pos] = fkey(sv); lout[pos] = __ldg(orow + j); }
                    }
                }
                __syncthreads();
                nl = s_nlist;
                if (nl >= KSEL && nl <= LISTCAP){ ok = true; break; }
                if (nl > LISTCAP) lo = tk2; else hi = tk2;
            }
        }

        const bool useList = ok;
        const int  ncand   = ok ? nl : VDIM;

        // ---------------- top-2 keys over candidate set ----------------
        unsigned t2a = 0, t2b = 0;
        {
            const int nit = (ncand + NTH - 1) / NTH;
            for (int it = 0; it < nit; ++it){
                int i = it*NTH + tid;
                if (i < ncand){
                    unsigned u;
                    if (useList) u = lkey[i];
                    else {
                        float f = srow[i];
                        u = (i == tgt || i == IGNORE_IDX) ? 0u : fkey(f);
                    }
                    if (u > t2a){ t2b = t2a; t2a = u; } else if (u > t2b) t2b = u;
                }
            }
        }
        #pragma unroll
        for (int o = 16; o; o >>= 1){
            unsigned ya = __shfl_xor_sync(FULLM, t2a, o);
            unsigned yb = __shfl_xor_sync(FULLM, t2b, o);
            if (ya > t2a){ t2b = max(t2a, yb); t2a = ya; }
            else         { t2b = max(t2b, ya); }
        }
        if (!lane){ s_t2a[wid] = t2a; s_t2b[wid] = t2b; }
        __syncthreads();
        if (wid == 0){
            unsigned xa = (lane < NW) ? s_t2a[lane] : 0u;
            unsigned xb = (lane < NW) ? s_t2b[lane] : 0u;
            #pragma unroll
            for (int o = 4; o; o >>= 1){
                unsigned ya = __shfl_xor_sync(FULLM, xa, o);
                unsigned yb = __shfl_xor_sync(FULLM, xb, o);
                if (ya > xa){ xb = max(xa, yb); xa = ya; }
                else        { xb = max(xb, ya); }
            }
            if (!lane) s_t2b[0] = xb;
        }
        __syncthreads();
        const unsigned k2key = s_t2b[0];
        const float    s2    = kinv(k2key);

        // ---------------- exact 500th-largest ----------------
        unsigned kthkey;
        if (useList){
            kthkey = radix_select(lkey, ncand, KSEL, hists, s_wtot, &s_selb, &s_selk);
        } else {
            unsigned prefix = 0, kk = KSEL;
            for (int shift = 24; shift >= 0; shift -= 8){
                hists[tid] = 0;
                __syncthreads();
                const bool first = (shift == 24);
                const unsigned pref_hi = first ? 0u : (prefix >> (shift + 8));
                const int nit = (VDIM + NTH - 1) / NTH;
                for (int it = 0; it < nit; ++it){
                    int i = it*NTH + tid;
                    bool in = i < VDIM;
                    unsigned u = 0u;
                    if (in){
                        float f = srow[i];
                        u = (i == tgt || i == IGNORE_IDX) ? 0u : fkey(f);
                    }
                    bool okd = in && (first || (u >> (shift + 8)) == pref_hi);
                    unsigned d = (u >> shift) & 255u;
                    unsigned tag = okd ? d : (0x100u + (unsigned)lane);
                    unsigned mm = __match_any_sync(FULLM, tag);
                    if (okd && lane == (__ffs(mm) - 1))
                        atomicAdd(&hists[d], (unsigned)__popc(mm));
                }
                __syncthreads();
                unsigned b;
                select_bucket(hists, kk, b, s_wtot, &s_selb, &s_selk);
                prefix |= b << shift;
            }
            kthkey = prefix;
        }

        // ------------ final: Z, S1, S2 over kept keys in [kth, k2] ---------------
        float Z = 0.f, S1 = 0.f, S2 = 0.f;
        {
            const int nit = (ncand + NTH - 1) / NTH;
            for (int it = 0; it < nit; ++it){
                int i = it*NTH + tid;
                if (i < ncand){
                    unsigned u; float ov;
                    if (useList){ u = lkey[i]; ov = lout[i]; }
                    else {
                        float f = srow[i];
                        u = (i == tgt || i == IGNORE_IDX) ? 0u : fkey(f);
                        ov = 0.f;
                    }
                    if (u >= kthkey && u <= k2key){
                        if (!useList) ov = __ldg(orow + i);
                        float sv = kinv(u);
                        float e = expf(sv - s2);
                        Z  += e;
                        S1 += e * sv;
                        S2 += e * ov;
                    }
                }
            }
        }
        #pragma unroll
        for (int o = 16; o; o >>= 1){
            Z  += __shfl_xor_sync(FULLM, Z,  o);
            S1 += __shfl_xor_sync(FULLM, S1, o);
            S2 += __shfl_xor_sync(FULLM, S2, o);
        }
        if (!lane){ s_f0[wid] = Z; s_f1[wid] = S1; s_f2[wid] = S2; }
        __syncthreads();
        if (wid == 0){
            float av = (lane < NW) ? s_f0[lane] : 0.f;
            float bv = (lane < NW) ? s_f1[lane] : 0.f;
            float cv = (lane < NW) ? s_f2[lane] : 0.f;
            #pragma unroll
            for (int o = 4; o; o >>= 1){
                av += __shfl_xor_sync(FULLM, av, o);
                bv += __shfl_xor_sync(FULLM, bv, o);
                cv += __shfl_xor_sync(FULLM, cv, o);
            }
            if (!lane){
                float loss = 0.f;
                if (tgt != IGNORE_IDX){
                    float Zt = av, S1t = bv, S2t = cv;
                    float vmax = 1.0f / Zt;
                    float pm = expf(o_max);
                    float pg = expf(o_t);
                    float eps0 = 1.0f - pm;
                    float ub   = 1.0f / (1.0f + vmax) - MARGIN_C;
                    float eps1 = (eps0 > ub) ? ub : eps0;
                    float al = pg / pm; al *= al;
                    float eps = al * eps1;
                    float conf = 1.0f - eps;
                    if (eps  > 0.f) loss += eps  * (logf(eps)  - s2 - logf(Zt) + (S1t - S2t) / Zt);
                    if (conf > 0.f) loss += conf * (logf(conf) - o_t);
                }
                g_rowloss[row] = loss;
            }
        }
    }

    // ---------------- CTA completion + last-CTA final reduction ----------------
    __syncthreads();
    if (tid == 0){
        __threadfence();
        unsigned t = atomicAdd(&g_done, 1u);
        s_last = (t == NCTA - 1u) ? 1 : 0;
    }
    __syncthreads();

    if (s_last){
        __threadfence();
        __shared__ double sd8[NW];
        double s = 0.0;
        for (int i = tid; i < BDIM; i += NTH) s += (double)g_rowloss[i];
        #pragma unroll
        for (int o = 16; o; o >>= 1) s += __shfl_xor_sync(FULLM, s, o);
        if (!lane) sd8[wid] = s;
        __syncthreads();
        if (tid == 0){
            double x = 0.0;
            #pragma unroll
            for (int w = 0; w < NW; ++w) x += sd8[w];
            out[0] = (float)x;
            g_done = 0;
            g_row  = 0;
        }
    }
}

extern "C" void kernel_launch(void* const* d_in, const int* in_sizes, int n_in,
                              void* d_out, int out_size)
{
    const float* output = (const float*)d_in[0];
    const int*   target = (const int*)d_in[1];
    const float* scores = (const float*)d_in[2];

    size_t dyn = (size_t)(4*CHUNK + 2*LISTCAP) * 4;   // 96 KB
    cudaFuncSetAttribute(adalab_kernel,
                         cudaFuncAttributeMaxDynamicSharedMemorySize, (int)dyn);

    adalab_kernel<<<NCTA, NTH, dyn>>>(output, target, scores, (float*)d_out);
}

// round 16
// speedup vs baseline: 1.4650x; 1.4650x over previous
#include <cuda_runtime.h>

#define VDIM   50257
#define BDIM   2048
#define KSEL   500
#define NTH    256
#define NW     8
#define LISTCAP 4096
#define SVCH   4            // 4 chunks * 256 threads * float4 = 4096 samples
#define ZCOEF  2.10f        // expected ~930 candidates on N(0,1); 7.8-sigma from 500 edge
#define MARGIN_C 0.2f
#define IGNORE_IDX 0
#define FULLM 0xffffffffu
#define NCTA   592          // 148 SMs * 4 CTAs — exactly one wave

__device__ float    g_rowloss[BDIM];
__device__ unsigned g_done;
__device__ unsigned g_row;

static __device__ __forceinline__ unsigned fkey(float f){
    unsigned u = __float_as_uint(f);
    return (u & 0x80000000u) ? ~u : (u | 0x80000000u);
}
static __device__ __forceinline__ float kinv(unsigned u){
    unsigned b = (u & 0x80000000u) ? (u & 0x7FFFFFFFu) : ~u;
    return __uint_as_float(b);
}

static __device__ __forceinline__ void select_bucket(
    const unsigned* hists, unsigned& kk, unsigned& bucket,
    unsigned* wtot, unsigned* selb, unsigned* selk)
{
    const int tid = threadIdx.x;
    const int lane = tid & 31;
    unsigned cnt = hists[tid];
    unsigned s = cnt;
    #pragma unroll
    for (int o = 1; o < 32; o <<= 1){
        unsigned t = __shfl_down_sync(FULLM, s, o);
        if (lane + o < 32) s += t;
    }
    if (lane == 0) wtot[tid >> 5] = s;
    __syncthreads();
    unsigned Sb = s;
    for (int w = (tid >> 5) + 1; w < 8; ++w) Sb += wtot[w];
    unsigned Snext = Sb - cnt;
    if (Sb >= kk && Snext < kk){ *selb = (unsigned)tid; *selk = kk - Snext; }
    __syncthreads();
    bucket = *selb;
    kk = *selk;
    __syncthreads();
}

static __device__ unsigned radix_select(const unsigned* keys, int n, unsigned kk,
                                        unsigned* hists, unsigned* wtot,
                                        unsigned* selb, unsigned* selk)
{
    const int tid = threadIdx.x;
    const int lane = tid & 31;
    unsigned prefix = 0;
    for (int shift = 24; shift >= 0; shift -= 8){
        hists[tid] = 0;
        __syncthreads();
        const bool first = (shift == 24);
        const unsigned pref_hi = first ? 0u : (prefix >> (shift + 8));
        const int nit = (n + NTH - 1) / NTH;
        for (int it = 0; it < nit; ++it){
            int i = it*NTH + tid;
            bool in = i < n;
            unsigned u = in ? keys[i] : 0u;
            bool okd = in && (first || (u >> (shift + 8)) == pref_hi);
            unsigned d = (u >> shift) & 255u;
            unsigned tag = okd ? d : (0x100u + (unsigned)lane);
            unsigned mm = __match_any_sync(FULLM, tag);
            if (okd && lane == (__ffs(mm) - 1))
                atomicAdd(&hists[d], (unsigned)__popc(mm));
        }
        __syncthreads();
        unsigned b;
        select_bucket(hists, kk, b, wtot, selb, selk);
        prefix |= b << shift;
    }
    return prefix;
}

__global__ void __launch_bounds__(NTH, 4)
adalab_kernel(const float* __restrict__ output,
              const int*   __restrict__ target,
              const float* __restrict__ scores,
              float* __restrict__ out)
{
    __shared__ unsigned lkey[LISTCAP];
    __shared__ float    lout[LISTCAP];
    __shared__ unsigned hists[256];
    __shared__ float    s_f0[NW], s_f1[NW], s_f2[NW];
    __shared__ unsigned s_t2a[NW], s_t2b[NW];
    __shared__ unsigned s_wtot[8];
    __shared__ unsigned s_selb, s_selk;
    __shared__ int      s_nlist;
    __shared__ float    s_ot, s_stgt, s_s0, s_o0;
    __shared__ int      s_rm;
    __shared__ int      s_last;
    __shared__ int      s_row;

    const int tid  = threadIdx.x;
    const int lane = tid & 31;
    const int wid  = tid >> 5;
    const float NEGINF = __int_as_float(0xff800000);

    while (true){
        __syncthreads();               // protect shared reuse across rows
        if (tid == 0) s_row = (int)atomicAdd(&g_row, 1u);
        __syncthreads();
        const int row = s_row;
        if (row >= BDIM) break;

        const int tgt  = target[row];
        const float* orow = output + (size_t)row * VDIM;
        const float* srow = scores + (size_t)row * VDIM;

        const int a    = (int)((4u - ((unsigned)((size_t)row * VDIM) & 3u)) & 3u);
        const int nvec = (VDIM - a) >> 2;
        const int vend = a + nvec * 4;

        if (tid == 0){
            s_ot   = __ldg(orow + tgt);
            s_stgt = __ldg(srow + tgt);
            s_s0   = __ldg(srow + IGNORE_IDX);
            s_o0   = __ldg(orow + IGNORE_IDX);
        }

        // ------- sample pass (vectorized): mean + ZCOEF*sigma of 4096 samples ----
        float sum = 0.f, sq = 0.f;
        #pragma unroll
        for (int c = 0; c < SVCH; ++c){
            int qb = (c * (nvec - NTH)) / (SVCH - 1);
            float4 s4 = __ldg(reinterpret_cast<const float4*>(srow + a + (qb + tid)*4));
            sum += (s4.x + s4.y) + (s4.z + s4.w);
            sq = fmaf(s4.x, s4.x, sq); sq = fmaf(s4.y, s4.y, sq);
            sq = fmaf(s4.z, s4.z, sq); sq = fmaf(s4.w, s4.w, sq);
        }
        #pragma unroll
        for (int o = 16; o; o >>= 1){
            sum += __shfl_xor_sync(FULLM, sum, o);
            sq  += __shfl_xor_sync(FULLM, sq,  o);
        }
        if (!lane){ s_f1[wid] = sum; s_f2[wid] = sq; }
        __syncthreads();
        if (wid == 0){
            float u = (lane < NW) ? s_f1[lane] : 0.f;
            float v = (lane < NW) ? s_f2[lane] : 0.f;
            #pragma unroll
            for (int o = 4; o; o >>= 1){
                u += __shfl_xor_sync(FULLM, u, o);
                v += __shfl_xor_sync(FULLM, v, o);
            }
            if (!lane){ s_f1[0] = u; s_f2[0] = v; }
        }
        __syncthreads();
        {
            const float inv_n = 1.0f / (SVCH * NTH * 4);
            float mean = s_f1[0] * inv_n;
            float var  = fmaxf(s_f2[0] * inv_n - mean*mean, 1e-12f);
            if (tid == 0) s_f0[0] = mean + ZCOEF * sqrtf(var);
        }
        __syncthreads();
        unsigned tkey = fkey(s_f0[0]);

        // ----- fused full pass: omax + compaction (no index checks in hot loop) --
        float omax = NEGINF;
        {
            __syncthreads();
            if (tid == 0) s_nlist = 0;
            __syncthreads();
            const float T = kinv(tkey);
            {
                int j = tid;
                if (j < a){
                    float o = __ldcs(orow + j); omax = fmaxf(omax, o);
                    float sv = srow[j];
                    if (sv >= T){
                        int pos = atomicAdd(&s_nlist, 1);
                        if (pos < LISTCAP){ lkey[pos] = fkey(sv); lout[pos] = o; }
                    }
                }
                j = vend + tid;
                if (j < VDIM){
                    float o = __ldcs(orow + j); omax = fmaxf(omax, o);
                    float sv = srow[j];
                    if (sv >= T){
                        int pos = atomicAdd(&s_nlist, 1);
                        if (pos < LISTCAP){ lkey[pos] = fkey(sv); lout[pos] = o; }
                    }
                }
            }
            int q = tid;
            for (; q + 3*NTH < nvec; q += 4*NTH){
                int j1 = a + q*4, j2 = a + (q + NTH)*4, j3 = a + (q + 2*NTH)*4, j4 = a + (q + 3*NTH)*4;
                float4 o41 = __ldcs(reinterpret_cast<const float4*>(orow + j1));
                float4 o42 = __ldcs(reinterpret_cast<const float4*>(orow + j2));
                float4 o43 = __ldcs(reinterpret_cast<const float4*>(orow + j3));
                float4 o44 = __ldcs(reinterpret_cast<const float4*>(orow + j4));
                float4 s41 = *reinterpret_cast<const float4*>(srow + j1);
                float4 s42 = *reinterpret_cast<const float4*>(srow + j2);
                float4 s43 = *reinterpret_cast<const float4*>(srow + j3);
                float4 s44 = *reinterpret_cast<const float4*>(srow + j4);
                omax = fmaxf(omax, fmaxf(fmaxf(o41.x, o41.y), fmaxf(o41.z, o41.w)));
                omax = fmaxf(omax, fmaxf(fmaxf(o42.x, o42.y), fmaxf(o42.z, o42.w)));
                omax = fmaxf(omax, fmaxf(fmaxf(o43.x, o43.y), fmaxf(o43.z, o43.w)));
                omax = fmaxf(omax, fmaxf(fmaxf(o44.x, o44.y), fmaxf(o44.z, o44.w)));
                #define EMIT(sv, ov) \
                    if ((sv) >= T){ \
                        int pos = atomicAdd(&s_nlist, 1); \
                        if (pos < LISTCAP){ lkey[pos] = fkey(sv); lout[pos] = (ov); } \
                    }
                EMIT(s41.x, o41.x) EMIT(s41.y, o41.y) EMIT(s41.z, o41.z) EMIT(s41.w, o41.w)
                EMIT(s42.x, o42.x) EMIT(s42.y, o42.y) EMIT(s42.z, o42.z) EMIT(s42.w, o42.w)
                EMIT(s43.x, o43.x) EMIT(s43.y, o43.y) EMIT(s43.z, o43.z) EMIT(s43.w, o43.w)
                EMIT(s44.x, o44.x) EMIT(s44.y, o44.y) EMIT(s44.z, o44.z) EMIT(s44.w, o44.w)
            }
            for (; q < nvec; q += NTH){
                int j1 = a + q*4;
                float4 o4 = __ldcs(reinterpret_cast<const float4*>(orow + j1));
                float4 s4 = *reinterpret_cast<const float4*>(srow + j1);
                omax = fmaxf(omax, fmaxf(fmaxf(o4.x, o4.y), fmaxf(o4.z, o4.w)));
                EMIT(s4.x, o4.x) EMIT(s4.y, o4.y) EMIT(s4.z, o4.z) EMIT(s4.w, o4.w)
                #undef EMIT
            }
        }
        // reduce omax
        #pragma unroll
        for (int o = 16; o; o >>= 1) omax = fmaxf(omax, __shfl_xor_sync(FULLM, omax, o));
        if (!lane) s_f0[wid] = omax;
        __syncthreads();
        if (wid == 0){
            float x = (lane < NW) ? s_f0[lane] : NEGINF;
            #pragma unroll
            for (int o = 4; o; o >>= 1) x = fmaxf(x, __shfl_xor_sync(FULLM, x, o));
            if (!lane) s_f0[0] = x;
        }
        __syncthreads();
        const float o_max = s_f0[0];
        const float o_t   = s_ot;

        int nl = s_nlist;

        // ------------- exact removal of tgt / ignore entries (if captured) -------
        if (nl <= LISTCAP){
            const float T = kinv(tkey);
            #pragma unroll
            for (int vsel = 0; vsel < 2; ++vsel){
                if (vsel == 1 && tgt == IGNORE_IDX) break;
                float svict = (vsel == 0) ? s_stgt : s_s0;
                float ovict = (vsel == 0) ? s_ot   : s_o0;
                if (svict >= T){
                    unsigned kv = fkey(svict);
                    __syncthreads();
                    if (tid == 0) s_rm = 0x7fffffff;
                    __syncthreads();
                    for (int i = tid; i < nl; i += NTH)
                        if (lkey[i] == kv && lout[i] == ovict) atomicMin(&s_rm, i);
                    __syncthreads();
                    int rm = s_rm;
                    if (tid == 0 && rm < nl){
                        lkey[rm] = lkey[nl-1]; lout[rm] = lout[nl-1];
                        s_nlist = nl - 1;
                    }
                    __syncthreads();
                    nl = s_nlist;
                }
            }
        }
        bool ok = (nl >= KSEL && nl <= LISTCAP);

        // ------------- rare: binary-search rescan on threshold key ---------------
        if (!ok){
            unsigned lo = 0u, hi = 0xffffffffu;
            if (nl > LISTCAP) lo = tkey; else hi = tkey;
            for (int iter = 0; iter < 12 && hi - lo >= 2u; ++iter){
                tkey = lo + ((hi - lo) >> 1);
                __syncthreads();
                if (tid == 0) s_nlist = 0;
                __syncthreads();
                const float T = kinv(tkey);
                for (int j = tid; j < VDIM; j += NTH){
                    float sv = srow[j];
                    if (sv >= T && j != tgt && j != IGNORE_IDX){
                        int pos = atomicAdd(&s_nlist, 1);
                        if (pos < LISTCAP){ lkey[pos] = fkey(sv); lout[pos] = __ldg(orow + j); }
                    }
                }
                __syncthreads();
                nl = s_nlist;
                if (nl >= KSEL && nl <= LISTCAP){ ok = true; break; }
                if (nl > LISTCAP) lo = tkey; else hi = tkey;
            }
        }

        const bool useList = ok;
        const int  ncand   = ok ? nl : VDIM;

        // ---------------- top-2 keys over candidate set ----------------
        unsigned t2a = 0, t2b = 0;
        {
            const int nit = (ncand + NTH - 1) / NTH;
            for (int it = 0; it < nit; ++it){
                int i = it*NTH + tid;
                if (i < ncand){
                    unsigned u;
                    if (useList) u = lkey[i];
                    else {
                        float f = srow[i];
                        u = (i == tgt || i == IGNORE_IDX) ? 0u : fkey(f);
                    }
                    if (u > t2a){ t2b = t2a; t2a = u; } else if (u > t2b) t2b = u;
                }
            }
        }
        #pragma unroll
        for (int o = 16; o; o >>= 1){
            unsigned ya = __shfl_xor_sync(FULLM, t2a, o);
            unsigned yb = __shfl_xor_sync(FULLM, t2b, o);
            if (ya > t2a){ t2b = max(t2a, yb); t2a = ya; }
            else         { t2b = max(t2b, ya); }
        }
        if (!lane){ s_t2a[wid] = t2a; s_t2b[wid] = t2b; }
        __syncthreads();
        if (wid == 0){
            unsigned xa = (lane < NW) ? s_t2a[lane] : 0u;
            unsigned xb = (lane < NW) ? s_t2b[lane] : 0u;
            #pragma unroll
            for (int o = 4; o; o >>= 1){
                unsigned ya = __shfl_xor_sync(FULLM, xa, o);
                unsigned yb = __shfl_xor_sync(FULLM, xb, o);
                if (ya > xa){ xb = max(xa, yb); xa = ya; }
                else        { xb = max(xb, ya); }
            }
            if (!lane) s_t2b[0] = xb;
        }
        __syncthreads();
        const unsigned k2key = s_t2b[0];
        const float    s2    = kinv(k2key);

        // ---------------- exact 500th-largest ----------------
        unsigned kthkey;
        if (useList){
            kthkey = radix_select(lkey, ncand, KSEL, hists, s_wtot, &s_selb, &s_selk);
        } else {
            unsigned prefix = 0, kk = KSEL;
            for (int shift = 24; shift >= 0; shift -= 8){
                hists[tid] = 0;
                __syncthreads();
                const bool first = (shift == 24);
                const unsigned pref_hi = first ? 0u : (prefix >> (shift + 8));
                const int nit = (VDIM + NTH - 1) / NTH;
                for (int it = 0; it < nit; ++it){
                    int i = it*NTH + tid;
                    bool in = i < VDIM;
                    unsigned u = 0u;
                    if (in){
                        float f = srow[i];
                        u = (i == tgt || i == IGNORE_IDX) ? 0u : fkey(f);
                    }
                    bool okd = in && (first || (u >> (shift + 8)) == pref_hi);
                    unsigned d = (u >> shift) & 255u;
                    unsigned tag = okd ? d : (0x100u + (unsigned)lane);
                    unsigned mm = __match_any_sync(FULLM, tag);
                    if (okd && lane == (__ffs(mm) - 1))
                        atomicAdd(&hists[d], (unsigned)__popc(mm));
                }
                __syncthreads();
                unsigned b;
                select_bucket(hists, kk, b, s_wtot, &s_selb, &s_selk);
                prefix |= b << shift;
            }
            kthkey = prefix;
        }

        // ------------ final: Z, S1, S2 over kept keys in [kth, k2] ---------------
        float Z = 0.f, S1 = 0.f, S2 = 0.f;
        {
            const int nit = (ncand + NTH - 1) / NTH;
            for (int it = 0; it < nit; ++it){
                int i = it*NTH + tid;
                if (i < ncand){
                    unsigned u; float ov;
                    if (useList){ u = lkey[i]; ov = lout[i]; }
                    else {
                        float f = srow[i];
                        u = (i == tgt || i == IGNORE_IDX) ? 0u : fkey(f);
                        ov = 0.f;
                    }
                    if (u >= kthkey && u <= k2key){
                        if (!useList) ov = __ldg(orow + i);
                        float sv = kinv(u);
                        float e = expf(sv - s2);
                        Z  += e;
                        S1 += e * sv;
                        S2 += e * ov;
                    }
                }
            }
        }
        #pragma unroll
        for (int o = 16; o; o >>= 1){
            Z  += __shfl_xor_sync(FULLM, Z,  o);
            S1 += __shfl_xor_sync(FULLM, S1, o);
            S2 += __shfl_xor_sync(FULLM, S2, o);
        }
        if (!lane){ s_f0[wid] = Z; s_f1[wid] = S1; s_f2[wid] = S2; }
        __syncthreads();
        if (wid == 0){
            float av = (lane < NW) ? s_f0[lane] : 0.f;
            float bv = (lane < NW) ? s_f1[lane] : 0.f;
            float cv = (lane < NW) ? s_f2[lane] : 0.f;
            #pragma unroll
            for (int o = 4; o; o >>= 1){
                av += __shfl_xor_sync(FULLM, av, o);
                bv += __shfl_xor_sync(FULLM, bv, o);
                cv += __shfl_xor_sync(FULLM, cv, o);
            }
            if (!lane){
                float loss = 0.f;
                if (tgt != IGNORE_IDX){
                    float Zt = av, S1t = bv, S2t = cv;
                    float vmax = 1.0f / Zt;
                    float pm = expf(o_max);
                    float pg = expf(o_t);
                    float eps0 = 1.0f - pm;
                    float ub   = 1.0f / (1.0f + vmax) - MARGIN_C;
                    float eps1 = (eps0 > ub) ? ub : eps0;
                    float al = pg / pm; al *= al;
                    float eps = al * eps1;
                    float conf = 1.0f - eps;
                    if (eps  > 0.f) loss += eps  * (logf(eps)  - s2 - logf(Zt) + (S1t - S2t) / Zt);
                    if (conf > 0.f) loss += conf * (logf(conf) - o_t);
                }
                g_rowloss[row] = loss;
            }
        }
    }

    // ---------------- CTA completion + last-CTA final reduction ----------------
    __syncthreads();
    if (tid == 0){
        __threadfence();
        unsigned t = atomicAdd(&g_done, 1u);
        s_last = (t == NCTA - 1u) ? 1 : 0;
    }
    __syncthreads();

    if (s_last){
        __threadfence();
        __shared__ double sd8[NW];
        double s = 0.0;
        for (int i = tid; i < BDIM; i += NTH) s += (double)g_rowloss[i];
        #pragma unroll
        for (int o = 16; o; o >>= 1) s += __shfl_xor_sync(FULLM, s, o);
        if (!lane) sd8[wid] = s;
        __syncthreads();
        if (tid == 0){
            double x = 0.0;
            #pragma unroll
            for (int w = 0; w < NW; ++w) x += sd8[w];
            out[0] = (float)x;
            g_done = 0;
            g_row  = 0;
        }
    }
}

extern "C" void kernel_launch(void* const* d_in, const int* in_sizes, int n_in,
                              void* d_out, int out_size)
{
    const float* output = (const float*)d_in[0];
    const int*   target = (const int*)d_in[1];
    const float* scores = (const float*)d_in[2];

    adalab_kernel<<<NCTA, NTH>>>(output, target, scores, (float*)d_out);
}